// round 11
// baseline (speedup 1.0000x reference)
#include <cuda_runtime.h>
#include <cuda_bf16.h>
#include <cstdint>
#include <cstddef>

typedef unsigned long long ull;

#define BSZ   256
#define INK   2048
#define NCF   1000
#define NCP   1024
#define ODEC  4096
#define NDEC  16384
#define NEG_SLOPE 0.1f

#define BK    32
#define NKT   (INK / BK)       // 64 ktiles per pass
#define NIT   (3 * NKT)        // 192
#define STAGE_BYTES 24576      // A 8K + B 16K
#define NSTG  3
#define SMEM_DYN (NSTG * STAGE_BYTES)

// bf16 hi/lo scratch
__device__ __nv_bfloat16 g_xh[BSZ * INK];
__device__ __nv_bfloat16 g_xl[BSZ * INK];
__device__ __nv_bfloat16 g_w1h[(size_t)NDEC * INK];
__device__ __nv_bfloat16 g_w1l[(size_t)NDEC * INK];
__device__ __nv_bfloat16 g_fwh[(size_t)NCP * INK];
__device__ __nv_bfloat16 g_fwl[(size_t)NCP * INK];

// ---------------------------------------------------------------------------
__device__ __forceinline__ uint32_t smem_u32(const void* p) {
    return (uint32_t)__cvta_generic_to_shared(p);
}
__device__ __forceinline__ void cpasync16(uint32_t dst, const void* src) {
    asm volatile("cp.async.cg.shared.global [%0], [%1], 16;" :: "r"(dst), "l"(src));
}
__device__ __forceinline__ void cpcommit() {
    asm volatile("cp.async.commit_group;");
}
__device__ __forceinline__ void ldsm4(uint32_t& r0, uint32_t& r1, uint32_t& r2,
                                      uint32_t& r3, uint32_t addr) {
    asm volatile("ldmatrix.sync.aligned.m8n8.x4.shared.b16 {%0,%1,%2,%3}, [%4];"
                 : "=r"(r0), "=r"(r1), "=r"(r2), "=r"(r3) : "r"(addr));
}
__device__ __forceinline__ void mma16816(float* d, const uint32_t* a, const uint32_t* b) {
    asm volatile(
        "mma.sync.aligned.m16n8k16.row.col.f32.bf16.bf16.f32 "
        "{%0,%1,%2,%3}, {%4,%5,%6,%7}, {%8,%9}, {%0,%1,%2,%3};"
        : "+f"(d[0]), "+f"(d[1]), "+f"(d[2]), "+f"(d[3])
        : "r"(a[0]), "r"(a[1]), "r"(a[2]), "r"(a[3]), "r"(b[0]), "r"(b[1]));
}

// ---------------------------------------------------------------------------
// Conversion kernels: fp32 -> bf16 hi/lo split
// ---------------------------------------------------------------------------
__device__ __forceinline__ ull pk4(__nv_bfloat16 a, __nv_bfloat16 b,
                                   __nv_bfloat16 c, __nv_bfloat16 d) {
    return (ull)__bfloat16_as_ushort(a)
         | ((ull)__bfloat16_as_ushort(b) << 16)
         | ((ull)__bfloat16_as_ushort(c) << 32)
         | ((ull)__bfloat16_as_ushort(d) << 48);
}
__device__ __forceinline__ void split1(float v, __nv_bfloat16& h, __nv_bfloat16& l) {
    h = __float2bfloat16_rn(v);
    l = __float2bfloat16_rn(v - __bfloat162float(h));
}

__global__ void conv_x_kernel(const float* __restrict__ x) {
    int t = blockIdx.x * blockDim.x + threadIdx.x;   // float4 idx
    float4 v = ((const float4*)x)[t];
    __nv_bfloat16 h0,h1,h2,h3,l0,l1,l2,l3;
    split1(v.x,h0,l0); split1(v.y,h1,l1); split1(v.z,h2,l2); split1(v.w,h3,l3);
    ((ull*)g_xh)[t] = pk4(h0,h1,h2,h3);
    ((ull*)g_xl)[t] = pk4(l0,l1,l2,l3);
}

// W1[o][i][h] -> rows n=o*4+h, k=i. Direct warp-coalesced 2B stores.
__global__ __launch_bounds__(256)
void conv_w1_kernel(const float* __restrict__ W1) {
    const int o = blockIdx.x;
    const int t = threadIdx.x;
    const float4* src = (const float4*)(W1 + (size_t)o * 8192);
    #pragma unroll
    for (int q = 0; q < 8; q++) {
        const int i = t + q * 256;                 // k index
        float4 v = src[i];
        float vv[4] = {v.x, v.y, v.z, v.w};
        #pragma unroll
        for (int h = 0; h < 4; h++) {
            __nv_bfloat16 bh, bl;
            split1(vv[h], bh, bl);
            const size_t off = (size_t)(o * 4 + h) * INK + i;
            g_w1h[off] = bh;
            g_w1l[off] = bl;
        }
    }
}

__global__ void conv_fcw_kernel(const float* __restrict__ fcW) {
    const int n = blockIdx.x;                // 0..1023
    const int t = threadIdx.x;
    const int base = t * 8;
    __nv_bfloat16 hb[8], lb[8];
    if (n < NCF) {
        const float4* src = (const float4*)(fcW + (size_t)n * INK + base);
        float4 a = src[0], b = src[1];
        float vv[8] = {a.x,a.y,a.z,a.w,b.x,b.y,b.z,b.w};
        #pragma unroll
        for (int j = 0; j < 8; j++) split1(vv[j], hb[j], lb[j]);
    } else {
        #pragma unroll
        for (int j = 0; j < 8; j++) { hb[j] = __float2bfloat16(0.f); lb[j] = __float2bfloat16(0.f); }
    }
    ull* dh = (ull*)(g_fwh + (size_t)n * INK + base);
    ull* dl = (ull*)(g_fwl + (size_t)n * INK + base);
    dh[0] = pk4(hb[0],hb[1],hb[2],hb[3]); dh[1] = pk4(hb[4],hb[5],hb[6],hb[7]);
    dl[0] = pk4(lb[0],lb[1],lb[2],lb[3]); dl[1] = pk4(lb[4],lb[5],lb[6],lb[7]);
}

// ---------------------------------------------------------------------------
// mma.sync GEMM: CTA 128m x 256n, 8 warps of 64m x 64n.
// 3 passes (ah*bh + ah*bl + al*bh).
// smem per stage: A [128 rows x 64B] @0, B [256 rows x 64B] @8192.
// 16B chunks swizzled by c ^ ((row>>1)&3).
// ---------------------------------------------------------------------------
template<bool IS_FC>
__global__ __launch_bounds__(256, 1)
void mma_kernel(const float* __restrict__ b1, const float* __restrict__ W2,
                const float* __restrict__ b2, const float* __restrict__ fcb,
                float* __restrict__ out)
{
    extern __shared__ __align__(1024) char smbuf[];

    const int tid = threadIdx.x;
    const int lane = tid & 31;
    const int w = tid >> 5;
    const int warpm = w >> 2;       // 0..1  (64 m each)
    const int warpn = w & 3;        // 0..3  (64 n each)
    const int m0 = blockIdx.y * 128;
    const int n0 = blockIdx.x * 256;
    const uint32_t sm_u = smem_u32(smbuf);

    const __nv_bfloat16* Bh = IS_FC ? g_fwh : g_w1h;
    const __nv_bfloat16* Bl = IS_FC ? g_fwl : g_w1l;

    float acc[4][8][4];
    #pragma unroll
    for (int mi = 0; mi < 4; mi++)
        #pragma unroll
        for (int ni = 0; ni < 8; ni++)
            #pragma unroll
            for (int q = 0; q < 4; q++) acc[mi][ni][q] = 0.f;

    // --- cp.async slots: A 2 chunks/thread, B 4 chunks/thread ---
    const int arow_ld = tid >> 1;               // 0..127
    const int ac0     = (tid & 1) * 2;
    uint32_t dstA[2], dstB[4];
    size_t srcA[2], srcB[4];
    #pragma unroll
    for (int q = 0; q < 2; q++) {
        const int c = ac0 + q;
        const int cs = c ^ ((arow_ld >> 1) & 3);
        dstA[q] = (uint32_t)(arow_ld * 64 + cs * 16);
        srcA[q] = (size_t)(m0 + arow_ld) * INK + c * 8;
    }
    #pragma unroll
    for (int q = 0; q < 4; q++) {
        const int cs = q ^ ((tid >> 1) & 3);
        dstB[q] = (uint32_t)(8192 + tid * 64 + cs * 16);
        srcB[q] = (size_t)(n0 + tid) * INK + q * 8;
    }

    auto do_load = [&](int stage, int it) {
        const int pass = it / NKT;
        const int kt   = it - pass * NKT;
        const __nv_bfloat16* A  = (pass < 2) ? g_xh : g_xl;
        const __nv_bfloat16* Bp = (pass == 1) ? Bl : Bh;
        const uint32_t base = sm_u + stage * STAGE_BYTES;
        const size_t koff = (size_t)kt * BK;
        #pragma unroll
        for (int q = 0; q < 2; q++)
            cpasync16(base + dstA[q], A + srcA[q] + koff);
        #pragma unroll
        for (int q = 0; q < 4; q++)
            cpasync16(base + dstB[q], Bp + srcB[q] + koff);
    };

    // --- ldmatrix lane addressing ---
    // A x4: lanes 0-7 rows m0-7, 8-15 rows m8-15 (chunk +0); 16-31 same rows chunk +1
    const int a_r  = (lane & 7) + ((lane >> 3) & 1) * 8;
    const int a_kh = (lane >> 4) & 1;
    uint32_t aRowOff[4]; int aXor[4];
    #pragma unroll
    for (int mi = 0; mi < 4; mi++) {
        const int m_r = warpm * 64 + mi * 16 + a_r;
        aRowOff[mi] = (uint32_t)(m_r * 64);
        aXor[mi] = (m_r >> 1) & 3;
    }
    // B x4: lanes 0-7 tile 2q chunk+0; 8-15 tile 2q chunk+1; 16-23 tile 2q+1 chunk+0; 24-31 +1
    const int b_r  = (lane & 7) + ((lane >> 4) & 1) * 8;   // row within 16-row pair
    const int b_kh = (lane >> 3) & 1;
    uint32_t bRowOff[4]; int bXor[4];
    #pragma unroll
    for (int bq = 0; bq < 4; bq++) {
        const int n_r = warpn * 64 + bq * 16 + b_r;
        bRowOff[bq] = (uint32_t)(8192 + n_r * 64);
        bXor[bq] = (n_r >> 1) & 3;
    }

    auto compute = [&](int stage) {
        const uint32_t base = sm_u + stage * STAGE_BYTES;
        #pragma unroll
        for (int ks = 0; ks < 2; ks++) {
            uint32_t af[4][4], bf[4][4];
            #pragma unroll
            for (int mi = 0; mi < 4; mi++) {
                const uint32_t ch = (uint32_t)(((ks * 2 + a_kh) ^ aXor[mi]) << 4);
                ldsm4(af[mi][0], af[mi][1], af[mi][2], af[mi][3],
                      base + aRowOff[mi] + ch);
            }
            #pragma unroll
            for (int bq = 0; bq < 4; bq++) {
                const uint32_t ch = (uint32_t)(((ks * 2 + b_kh) ^ bXor[bq]) << 4);
                ldsm4(bf[bq][0], bf[bq][1], bf[bq][2], bf[bq][3],
                      base + bRowOff[bq] + ch);
            }
            #pragma unroll
            for (int mi = 0; mi < 4; mi++)
                #pragma unroll
                for (int ni = 0; ni < 8; ni++)
                    mma16816(acc[mi][ni], af[mi], &bf[ni >> 1][(ni & 1) * 2]);
        }
    };

    // --- pipeline: 2 ahead, 3 stages ---
    do_load(0, 0); cpcommit();
    do_load(1, 1); cpcommit();

    for (int it = 0; it < NIT; it++) {
        asm volatile("cp.async.wait_group 1;" ::: "memory");
        __syncthreads();
        compute(it % NSTG);
        if (it + 2 < NIT) do_load((it + 2) % NSTG, it + 2);
        cpcommit();
    }

    // --- epilogue ---
    const int gid = lane >> 2;     // 0..7
    const int tq  = lane & 3;

    if (!IS_FC) {
        #pragma unroll
        for (int ni = 0; ni < 8; ni++) {
            const int nb = n0 + warpn * 64 + ni * 8 + tq * 2;
            const float b1v0 = __ldg(&b1[nb]),     w2v0 = __ldg(&W2[nb]);
            const float b1v1 = __ldg(&b1[nb + 1]), w2v1 = __ldg(&W2[nb + 1]);
            const int dec = nb >> 2;
            const float b2v = __ldg(&b2[dec]);
            #pragma unroll
            for (int mi = 0; mi < 4; mi++) {
                #pragma unroll
                for (int h2 = 0; h2 < 2; h2++) {
                    const int gm = m0 + warpm * 64 + mi * 16 + gid + h2 * 8;
                    float v0 = acc[mi][ni][h2 * 2 + 0] + b1v0;
                    float v1 = acc[mi][ni][h2 * 2 + 1] + b1v1;
                    v0 = v0 >= 0.f ? v0 : NEG_SLOPE * v0;
                    v1 = v1 >= 0.f ? v1 : NEG_SLOPE * v1;
                    float p = v0 * w2v0 + v1 * w2v1;
                    p += __shfl_xor_sync(0xffffffffu, p, 1);
                    if ((lane & 1) == 0)
                        out[(size_t)gm * ODEC + dec] = p + b2v;
                }
            }
        }
    } else {
        #pragma unroll
        for (int ni = 0; ni < 8; ni++) {
            const int nb = n0 + warpn * 64 + ni * 8 + tq * 2;
            float fb0 = 0.f, fb1 = 0.f;
            if (nb < NCF)     fb0 = __ldg(&fcb[nb]);
            if (nb + 1 < NCF) fb1 = __ldg(&fcb[nb + 1]);
            #pragma unroll
            for (int mi = 0; mi < 4; mi++) {
                #pragma unroll
                for (int h2 = 0; h2 < 2; h2++) {
                    const int gm = m0 + warpm * 64 + mi * 16 + gid + h2 * 8;
                    if (nb < NCF)
                        out[(size_t)gm * NCF + nb]     = acc[mi][ni][h2 * 2 + 0] + fb0;
                    if (nb + 1 < NCF)
                        out[(size_t)gm * NCF + nb + 1] = acc[mi][ni][h2 * 2 + 1] + fb1;
                }
            }
        }
    }
}

// ---------------------------------------------------------------------------
extern "C" void kernel_launch(void* const* d_in, const int* in_sizes, int n_in,
                              void* d_out, int out_size)
{
    const float* x   = (const float*)d_in[0];
    const float* fcW = (const float*)d_in[1];
    const float* fcb = (const float*)d_in[2];
    const float* W1  = (const float*)d_in[3];
    const float* b1  = (const float*)d_in[4];
    const float* W2  = (const float*)d_in[5];
    const float* b2  = (const float*)d_in[6];

    float* out1 = (float*)d_out;              // x1 [256,1000]
    float* out2 = out1 + BSZ * NCF;           // x2 [256,4096]

    cudaFuncSetAttribute(mma_kernel<false>, cudaFuncAttributeMaxDynamicSharedMemorySize, SMEM_DYN);
    cudaFuncSetAttribute(mma_kernel<true>,  cudaFuncAttributeMaxDynamicSharedMemorySize, SMEM_DYN);

    conv_x_kernel<<<512, 256>>>(x);
    conv_w1_kernel<<<4096, 256>>>(W1);
    conv_fcw_kernel<<<1024, 256>>>(fcW);

    mma_kernel<false><<<dim3(64, 2), 256, SMEM_DYN>>>(b1, W2, b2, nullptr, out2);
    mma_kernel<true><<<dim3(4, 2), 256, SMEM_DYN>>>(nullptr, nullptr, nullptr, fcb, out1);
}

// round 12
// speedup vs baseline: 1.8994x; 1.8994x over previous
#include <cuda_runtime.h>
#include <cuda_bf16.h>
#include <cstdint>
#include <cstddef>

typedef unsigned long long ull;

#define BSZ   256
#define INK   2048
#define NCF   1000
#define NCP   1024
#define ODEC  4096
#define NDEC  16384
#define NEG_SLOPE 0.1f

#define BK    32
#define NKT   (INK / BK)       // 64 ktiles per phase
#define NIT   (2 * NKT)        // 128: phase1 = ah*bh + al*bh, phase2 = ah*bl
#define STAGE_BYTES 32768      // Ah 8K @0, Al 8K @8192, B 16K @16384
#define NSTG  3
#define SMEM_DYN (NSTG * STAGE_BYTES)

// bf16 hi/lo scratch
__device__ __nv_bfloat16 g_xh[BSZ * INK];
__device__ __nv_bfloat16 g_xl[BSZ * INK];
__device__ __nv_bfloat16 g_w1h[(size_t)NDEC * INK];
__device__ __nv_bfloat16 g_w1l[(size_t)NDEC * INK];
__device__ __nv_bfloat16 g_fwh[(size_t)NCP * INK];
__device__ __nv_bfloat16 g_fwl[(size_t)NCP * INK];

// ---------------------------------------------------------------------------
__device__ __forceinline__ uint32_t smem_u32(const void* p) {
    return (uint32_t)__cvta_generic_to_shared(p);
}
__device__ __forceinline__ void cpasync16(uint32_t dst, const void* src) {
    asm volatile("cp.async.cg.shared.global [%0], [%1], 16;" :: "r"(dst), "l"(src));
}
__device__ __forceinline__ void cpcommit() {
    asm volatile("cp.async.commit_group;");
}
__device__ __forceinline__ void ldsm4(uint32_t& r0, uint32_t& r1, uint32_t& r2,
                                      uint32_t& r3, uint32_t addr) {
    asm volatile("ldmatrix.sync.aligned.m8n8.x4.shared.b16 {%0,%1,%2,%3}, [%4];"
                 : "=r"(r0), "=r"(r1), "=r"(r2), "=r"(r3) : "r"(addr));
}
__device__ __forceinline__ void mma16816(float* d, const uint32_t* a, const uint32_t* b) {
    asm volatile(
        "mma.sync.aligned.m16n8k16.row.col.f32.bf16.bf16.f32 "
        "{%0,%1,%2,%3}, {%4,%5,%6,%7}, {%8,%9}, {%0,%1,%2,%3};"
        : "+f"(d[0]), "+f"(d[1]), "+f"(d[2]), "+f"(d[3])
        : "r"(a[0]), "r"(a[1]), "r"(a[2]), "r"(a[3]), "r"(b[0]), "r"(b[1]));
}

__device__ __forceinline__ ull pk4(__nv_bfloat16 a, __nv_bfloat16 b,
                                   __nv_bfloat16 c, __nv_bfloat16 d) {
    return (ull)__bfloat16_as_ushort(a)
         | ((ull)__bfloat16_as_ushort(b) << 16)
         | ((ull)__bfloat16_as_ushort(c) << 32)
         | ((ull)__bfloat16_as_ushort(d) << 48);
}
__device__ __forceinline__ uint32_t pk2(__nv_bfloat16 a, __nv_bfloat16 b) {
    return (uint32_t)__bfloat16_as_ushort(a)
         | ((uint32_t)__bfloat16_as_ushort(b) << 16);
}
__device__ __forceinline__ void split1(float v, __nv_bfloat16& h, __nv_bfloat16& l) {
    h = __float2bfloat16_rn(v);
    l = __float2bfloat16_rn(v - __bfloat162float(h));
}

// ---------------------------------------------------------------------------
// Merged conversion kernel:
//   bx <  4096        : W1[o][i][h] -> rows n=o*4+h (smem transpose, wide I/O)
//   4096 <= bx < 4608 : x split
//   4608 <= bx < 5632 : fcW split (padded to 1024 rows)
// ---------------------------------------------------------------------------
__global__ __launch_bounds__(256)
void conv_all(const float* __restrict__ x, const float* __restrict__ W1,
              const float* __restrict__ fcW)
{
    __shared__ uint32_t sh_hi[4][1024];
    __shared__ uint32_t sh_lo[4][1024];

    const int bx = blockIdx.x;
    const int t = threadIdx.x;

    if (bx < 4096) {
        const int o = bx;
        const float4* src = (const float4*)(W1 + (size_t)o * 8192);
        #pragma unroll
        for (int q = 0; q < 4; q++) {
            const int j = t + q * 256;       // i-pair index, i = 2j, 2j+1
            float4 v0 = src[2 * j];
            float4 v1 = src[2 * j + 1];
            float a0[4] = {v0.x, v0.y, v0.z, v0.w};
            float a1[4] = {v1.x, v1.y, v1.z, v1.w};
            #pragma unroll
            for (int h = 0; h < 4; h++) {
                __nv_bfloat16 h0, l0, h1, l1;
                split1(a0[h], h0, l0);
                split1(a1[h], h1, l1);
                sh_hi[h][j] = pk2(h0, h1);
                sh_lo[h][j] = pk2(l0, l1);
            }
        }
        __syncthreads();
        #pragma unroll
        for (int h = 0; h < 4; h++) {
            const size_t row = (size_t)(o * 4 + h) * INK;
            ((uint4*)(g_w1h + row))[t] = ((const uint4*)sh_hi[h])[t];
            ((uint4*)(g_w1l + row))[t] = ((const uint4*)sh_lo[h])[t];
        }
    } else if (bx < 4608) {
        const int g = (bx - 4096) * 256 + t;     // float4 idx over x
        float4 v = ((const float4*)x)[g];
        __nv_bfloat16 h0,h1,h2,h3,l0,l1,l2,l3;
        split1(v.x,h0,l0); split1(v.y,h1,l1); split1(v.z,h2,l2); split1(v.w,h3,l3);
        ((ull*)g_xh)[g] = pk4(h0,h1,h2,h3);
        ((ull*)g_xl)[g] = pk4(l0,l1,l2,l3);
    } else {
        const int n = bx - 4608;                 // 0..1023
        const int base = t * 8;
        __nv_bfloat16 hb[8], lb[8];
        if (n < NCF) {
            const float4* src = (const float4*)(fcW + (size_t)n * INK + base);
            float4 a = src[0], b = src[1];
            float vv[8] = {a.x,a.y,a.z,a.w,b.x,b.y,b.z,b.w};
            #pragma unroll
            for (int j = 0; j < 8; j++) split1(vv[j], hb[j], lb[j]);
        } else {
            #pragma unroll
            for (int j = 0; j < 8; j++) { hb[j] = __float2bfloat16(0.f); lb[j] = __float2bfloat16(0.f); }
        }
        ull* dh = (ull*)(g_fwh + (size_t)n * INK + base);
        ull* dl = (ull*)(g_fwl + (size_t)n * INK + base);
        dh[0] = pk4(hb[0],hb[1],hb[2],hb[3]); dh[1] = pk4(hb[4],hb[5],hb[6],hb[7]);
        dl[0] = pk4(lb[0],lb[1],lb[2],lb[3]); dl[1] = pk4(lb[4],lb[5],lb[6],lb[7]);
    }
}

// ---------------------------------------------------------------------------
// Fused mma kernel: CTA 128m x 256n, 8 warps of 64m x 64n.
//   blockIdx.x < 64 : decoder tiles (B = w1 split, epilogue collapse)
//   blockIdx.x >= 64: fc tiles (B = fcw split, epilogue bias only)
// Phase 1 (it < 64):  ah*bh + al*bh   (Ah, Al, Bh loaded)
// Phase 2 (it >= 64): ah*bl           (Ah, Bl loaded)
// ---------------------------------------------------------------------------
__global__ __launch_bounds__(256, 1)
void mma_all(const float* __restrict__ b1, const float* __restrict__ W2,
             const float* __restrict__ b2, const float* __restrict__ fcb,
             float* __restrict__ out1, float* __restrict__ out2)
{
    extern __shared__ __align__(1024) char smbuf[];

    const int tid = threadIdx.x;
    const int lane = tid & 31;
    const int w = tid >> 5;
    const int warpm = w >> 2;       // 0..1  (64 m each)
    const int warpn = w & 3;        // 0..3  (64 n each)
    const bool is_fc = blockIdx.x >= 64;
    const int m0 = blockIdx.y * 128;
    const int n0 = (is_fc ? (blockIdx.x - 64) : blockIdx.x) * 256;
    const uint32_t sm_u = smem_u32(smbuf);

    const __nv_bfloat16* Bh = is_fc ? g_fwh : g_w1h;
    const __nv_bfloat16* Bl = is_fc ? g_fwl : g_w1l;

    float acc[4][8][4];
    #pragma unroll
    for (int mi = 0; mi < 4; mi++)
        #pragma unroll
        for (int ni = 0; ni < 8; ni++)
            #pragma unroll
            for (int q = 0; q < 4; q++) acc[mi][ni][q] = 0.f;

    // --- cp.async slots ---
    const int arow_ld = tid >> 1;               // 0..127
    const int ac0     = (tid & 1) * 2;
    uint32_t dstA[2], dstB[4];
    size_t srcA[2], srcB[4];
    #pragma unroll
    for (int q = 0; q < 2; q++) {
        const int c = ac0 + q;
        const int cs = c ^ ((arow_ld >> 1) & 3);
        dstA[q] = (uint32_t)(arow_ld * 64 + cs * 16);
        srcA[q] = (size_t)(m0 + arow_ld) * INK + c * 8;
    }
    #pragma unroll
    for (int q = 0; q < 4; q++) {
        const int cs = q ^ ((tid >> 1) & 3);
        dstB[q] = (uint32_t)(16384 + tid * 64 + cs * 16);
        srcB[q] = (size_t)(n0 + tid) * INK + q * 8;
    }

    auto do_load = [&](int stage, int it) {
        const bool ph1 = it < NKT;
        const int kt = ph1 ? it : it - NKT;
        const __nv_bfloat16* Bp = ph1 ? Bh : Bl;
        const uint32_t base = sm_u + stage * STAGE_BYTES;
        const size_t koff = (size_t)kt * BK;
        #pragma unroll
        for (int q = 0; q < 2; q++)
            cpasync16(base + dstA[q], g_xh + srcA[q] + koff);
        if (ph1) {
            #pragma unroll
            for (int q = 0; q < 2; q++)
                cpasync16(base + 8192 + dstA[q], g_xl + srcA[q] + koff);
        }
        #pragma unroll
        for (int q = 0; q < 4; q++)
            cpasync16(base + dstB[q], Bp + srcB[q] + koff);
    };

    // --- ldmatrix lane addressing ---
    const int a_r  = (lane & 7) + ((lane >> 3) & 1) * 8;
    const int a_kh = (lane >> 4) & 1;
    uint32_t aRowOff[4]; int aXor[4];
    #pragma unroll
    for (int mi = 0; mi < 4; mi++) {
        const int m_r = warpm * 64 + mi * 16 + a_r;
        aRowOff[mi] = (uint32_t)(m_r * 64);
        aXor[mi] = (m_r >> 1) & 3;
    }
    const int b_r  = (lane & 7) + ((lane >> 4) & 1) * 8;
    const int b_kh = (lane >> 3) & 1;
    uint32_t bRowOff[4]; int bXor[4];
    #pragma unroll
    for (int bq = 0; bq < 4; bq++) {
        const int n_r = warpn * 64 + bq * 16 + b_r;
        bRowOff[bq] = (uint32_t)(16384 + n_r * 64);
        bXor[bq] = (n_r >> 1) & 3;
    }

    auto compute = [&](int stage, bool ph1) {
        const uint32_t base = sm_u + stage * STAGE_BYTES;
        #pragma unroll
        for (int ks = 0; ks < 2; ks++) {
            uint32_t bfr[4][4];
            #pragma unroll
            for (int bq = 0; bq < 4; bq++) {
                const uint32_t ch = (uint32_t)(((ks * 2 + b_kh) ^ bXor[bq]) << 4);
                ldsm4(bfr[bq][0], bfr[bq][1], bfr[bq][2], bfr[bq][3],
                      base + bRowOff[bq] + ch);
            }
            uint32_t af[4][4];
            #pragma unroll
            for (int mi = 0; mi < 4; mi++) {
                const uint32_t ch = (uint32_t)(((ks * 2 + a_kh) ^ aXor[mi]) << 4);
                ldsm4(af[mi][0], af[mi][1], af[mi][2], af[mi][3],
                      base + aRowOff[mi] + ch);
            }
            #pragma unroll
            for (int mi = 0; mi < 4; mi++)
                #pragma unroll
                for (int ni = 0; ni < 8; ni++)
                    mma16816(acc[mi][ni], af[mi], &bfr[ni >> 1][(ni & 1) * 2]);
            if (ph1) {
                #pragma unroll
                for (int mi = 0; mi < 4; mi++) {
                    const uint32_t ch = (uint32_t)(((ks * 2 + a_kh) ^ aXor[mi]) << 4);
                    ldsm4(af[mi][0], af[mi][1], af[mi][2], af[mi][3],
                          base + 8192 + aRowOff[mi] + ch);
                }
                #pragma unroll
                for (int mi = 0; mi < 4; mi++)
                    #pragma unroll
                    for (int ni = 0; ni < 8; ni++)
                        mma16816(acc[mi][ni], af[mi], &bfr[ni >> 1][(ni & 1) * 2]);
            }
        }
    };

    // --- pipeline: 2 ahead, 3 stages ---
    do_load(0, 0); cpcommit();
    do_load(1, 1); cpcommit();

    for (int it = 0; it < NIT; it++) {
        asm volatile("cp.async.wait_group 1;" ::: "memory");
        __syncthreads();
        compute(it % NSTG, it < NKT);
        if (it + 2 < NIT) do_load((it + 2) % NSTG, it + 2);
        cpcommit();
    }

    // --- epilogue ---
    const int gid = lane >> 2;
    const int tq  = lane & 3;

    if (!is_fc) {
        #pragma unroll
        for (int ni = 0; ni < 8; ni++) {
            const int nb = n0 + warpn * 64 + ni * 8 + tq * 2;
            const float b1v0 = __ldg(&b1[nb]),     w2v0 = __ldg(&W2[nb]);
            const float b1v1 = __ldg(&b1[nb + 1]), w2v1 = __ldg(&W2[nb + 1]);
            const int dec = nb >> 2;
            const float b2v = __ldg(&b2[dec]);
            #pragma unroll
            for (int mi = 0; mi < 4; mi++) {
                #pragma unroll
                for (int h2 = 0; h2 < 2; h2++) {
                    const int gm = m0 + warpm * 64 + mi * 16 + gid + h2 * 8;
                    float v0 = acc[mi][ni][h2 * 2 + 0] + b1v0;
                    float v1 = acc[mi][ni][h2 * 2 + 1] + b1v1;
                    v0 = v0 >= 0.f ? v0 : NEG_SLOPE * v0;
                    v1 = v1 >= 0.f ? v1 : NEG_SLOPE * v1;
                    float p = v0 * w2v0 + v1 * w2v1;
                    p += __shfl_xor_sync(0xffffffffu, p, 1);
                    if ((lane & 1) == 0)
                        out2[(size_t)gm * ODEC + dec] = p + b2v;
                }
            }
        }
    } else {
        #pragma unroll
        for (int ni = 0; ni < 8; ni++) {
            const int nb = n0 + warpn * 64 + ni * 8 + tq * 2;
            float fb0 = 0.f, fb1 = 0.f;
            if (nb < NCF)     fb0 = __ldg(&fcb[nb]);
            if (nb + 1 < NCF) fb1 = __ldg(&fcb[nb + 1]);
            #pragma unroll
            for (int mi = 0; mi < 4; mi++) {
                #pragma unroll
                for (int h2 = 0; h2 < 2; h2++) {
                    const int gm = m0 + warpm * 64 + mi * 16 + gid + h2 * 8;
                    if (nb < NCF)
                        out1[(size_t)gm * NCF + nb]     = acc[mi][ni][h2 * 2 + 0] + fb0;
                    if (nb + 1 < NCF)
                        out1[(size_t)gm * NCF + nb + 1] = acc[mi][ni][h2 * 2 + 1] + fb1;
                }
            }
        }
    }
}

// ---------------------------------------------------------------------------
extern "C" void kernel_launch(void* const* d_in, const int* in_sizes, int n_in,
                              void* d_out, int out_size)
{
    const float* x   = (const float*)d_in[0];
    const float* fcW = (const float*)d_in[1];
    const float* fcb = (const float*)d_in[2];
    const float* W1  = (const float*)d_in[3];
    const float* b1  = (const float*)d_in[4];
    const float* W2  = (const float*)d_in[5];
    const float* b2  = (const float*)d_in[6];

    float* out1 = (float*)d_out;              // x1 [256,1000]
    float* out2 = out1 + BSZ * NCF;           // x2 [256,4096]

    cudaFuncSetAttribute(mma_all, cudaFuncAttributeMaxDynamicSharedMemorySize, SMEM_DYN);

    conv_all<<<5632, 256>>>(x, W1, fcW);
    mma_all<<<dim3(68, 2), 256, SMEM_DYN>>>(b1, W2, b2, fcb, out1, out2);
}

// round 13
// speedup vs baseline: 2.0433x; 1.0758x over previous
#include <cuda_runtime.h>
#include <cuda_bf16.h>
#include <cstdint>
#include <cstddef>

typedef unsigned long long ull;

#define BSZ   256
#define INK   2048
#define NCF   1000
#define NCP   1024
#define ODEC  4096
#define NDEC  16384
#define NEG_SLOPE 0.1f

#define BK    32
#define NIT   (INK / BK)       // 64 iterations, all 3 products per ktile
#define STAGE_BYTES 49152      // Ah 8K @0, Al 8K @8192, Bh 16K @16384, Bl 16K @32768
#define NSTG  3
#define SMEM_DYN (NSTG * STAGE_BYTES)

// bf16 hi/lo scratch
__device__ __nv_bfloat16 g_xh[BSZ * INK];
__device__ __nv_bfloat16 g_xl[BSZ * INK];
__device__ __nv_bfloat16 g_w1h[(size_t)NDEC * INK];
__device__ __nv_bfloat16 g_w1l[(size_t)NDEC * INK];
__device__ __nv_bfloat16 g_fwh[(size_t)NCP * INK];
__device__ __nv_bfloat16 g_fwl[(size_t)NCP * INK];

// ---------------------------------------------------------------------------
__device__ __forceinline__ uint32_t smem_u32(const void* p) {
    return (uint32_t)__cvta_generic_to_shared(p);
}
__device__ __forceinline__ void cpasync16(uint32_t dst, const void* src) {
    asm volatile("cp.async.cg.shared.global [%0], [%1], 16;" :: "r"(dst), "l"(src));
}
__device__ __forceinline__ void cpcommit() {
    asm volatile("cp.async.commit_group;");
}
__device__ __forceinline__ void ldsm4(uint32_t& r0, uint32_t& r1, uint32_t& r2,
                                      uint32_t& r3, uint32_t addr) {
    asm volatile("ldmatrix.sync.aligned.m8n8.x4.shared.b16 {%0,%1,%2,%3}, [%4];"
                 : "=r"(r0), "=r"(r1), "=r"(r2), "=r"(r3) : "r"(addr));
}
__device__ __forceinline__ void mma16816(float* d, const uint32_t* a, const uint32_t* b) {
    asm volatile(
        "mma.sync.aligned.m16n8k16.row.col.f32.bf16.bf16.f32 "
        "{%0,%1,%2,%3}, {%4,%5,%6,%7}, {%8,%9}, {%0,%1,%2,%3};"
        : "+f"(d[0]), "+f"(d[1]), "+f"(d[2]), "+f"(d[3])
        : "r"(a[0]), "r"(a[1]), "r"(a[2]), "r"(a[3]), "r"(b[0]), "r"(b[1]));
}

__device__ __forceinline__ ull pk4(__nv_bfloat16 a, __nv_bfloat16 b,
                                   __nv_bfloat16 c, __nv_bfloat16 d) {
    return (ull)__bfloat16_as_ushort(a)
         | ((ull)__bfloat16_as_ushort(b) << 16)
         | ((ull)__bfloat16_as_ushort(c) << 32)
         | ((ull)__bfloat16_as_ushort(d) << 48);
}
__device__ __forceinline__ uint32_t pk2(__nv_bfloat16 a, __nv_bfloat16 b) {
    return (uint32_t)__bfloat16_as_ushort(a)
         | ((uint32_t)__bfloat16_as_ushort(b) << 16);
}
__device__ __forceinline__ void split1(float v, __nv_bfloat16& h, __nv_bfloat16& l) {
    h = __float2bfloat16_rn(v);
    l = __float2bfloat16_rn(v - __bfloat162float(h));
}

// ---------------------------------------------------------------------------
// Merged conversion kernel (unchanged from R12 — near BW-bound)
// ---------------------------------------------------------------------------
__global__ __launch_bounds__(256)
void conv_all(const float* __restrict__ x, const float* __restrict__ W1,
              const float* __restrict__ fcW)
{
    __shared__ uint32_t sh_hi[4][1024];
    __shared__ uint32_t sh_lo[4][1024];

    const int bx = blockIdx.x;
    const int t = threadIdx.x;

    if (bx < 4096) {
        const int o = bx;
        const float4* src = (const float4*)(W1 + (size_t)o * 8192);
        #pragma unroll
        for (int q = 0; q < 4; q++) {
            const int j = t + q * 256;
            float4 v0 = src[2 * j];
            float4 v1 = src[2 * j + 1];
            float a0[4] = {v0.x, v0.y, v0.z, v0.w};
            float a1[4] = {v1.x, v1.y, v1.z, v1.w};
            #pragma unroll
            for (int h = 0; h < 4; h++) {
                __nv_bfloat16 h0, l0, h1, l1;
                split1(a0[h], h0, l0);
                split1(a1[h], h1, l1);
                sh_hi[h][j] = pk2(h0, h1);
                sh_lo[h][j] = pk2(l0, l1);
            }
        }
        __syncthreads();
        #pragma unroll
        for (int h = 0; h < 4; h++) {
            const size_t row = (size_t)(o * 4 + h) * INK;
            ((uint4*)(g_w1h + row))[t] = ((const uint4*)sh_hi[h])[t];
            ((uint4*)(g_w1l + row))[t] = ((const uint4*)sh_lo[h])[t];
        }
    } else if (bx < 4608) {
        const int g = (bx - 4096) * 256 + t;
        float4 v = ((const float4*)x)[g];
        __nv_bfloat16 h0,h1,h2,h3,l0,l1,l2,l3;
        split1(v.x,h0,l0); split1(v.y,h1,l1); split1(v.z,h2,l2); split1(v.w,h3,l3);
        ((ull*)g_xh)[g] = pk4(h0,h1,h2,h3);
        ((ull*)g_xl)[g] = pk4(l0,l1,l2,l3);
    } else {
        const int n = bx - 4608;
        const int base = t * 8;
        __nv_bfloat16 hb[8], lb[8];
        if (n < NCF) {
            const float4* src = (const float4*)(fcW + (size_t)n * INK + base);
            float4 a = src[0], b = src[1];
            float vv[8] = {a.x,a.y,a.z,a.w,b.x,b.y,b.z,b.w};
            #pragma unroll
            for (int j = 0; j < 8; j++) split1(vv[j], hb[j], lb[j]);
        } else {
            #pragma unroll
            for (int j = 0; j < 8; j++) { hb[j] = __float2bfloat16(0.f); lb[j] = __float2bfloat16(0.f); }
        }
        ull* dh = (ull*)(g_fwh + (size_t)n * INK + base);
        ull* dl = (ull*)(g_fwl + (size_t)n * INK + base);
        dh[0] = pk4(hb[0],hb[1],hb[2],hb[3]); dh[1] = pk4(hb[4],hb[5],hb[6],hb[7]);
        dl[0] = pk4(lb[0],lb[1],lb[2],lb[3]); dl[1] = pk4(lb[4],lb[5],lb[6],lb[7]);
    }
}

// ---------------------------------------------------------------------------
// Fused mma kernel: CTA 128m x 256n, 8 warps of 64m x 64n.
// All 3 products per ktile: (ah*bh) + (al*bh) with bh live, then (ah*bl).
// 64 iterations.
// ---------------------------------------------------------------------------
__global__ __launch_bounds__(256, 1)
void mma_all(const float* __restrict__ b1, const float* __restrict__ W2,
             const float* __restrict__ b2, const float* __restrict__ fcb,
             float* __restrict__ out1, float* __restrict__ out2)
{
    extern __shared__ __align__(1024) char smbuf[];

    const int tid = threadIdx.x;
    const int lane = tid & 31;
    const int w = tid >> 5;
    const int warpm = w >> 2;
    const int warpn = w & 3;
    const bool is_fc = blockIdx.x >= 64;
    const int m0 = blockIdx.y * 128;
    const int n0 = (is_fc ? (blockIdx.x - 64) : blockIdx.x) * 256;
    const uint32_t sm_u = smem_u32(smbuf);

    const __nv_bfloat16* Bh = is_fc ? g_fwh : g_w1h;
    const __nv_bfloat16* Bl = is_fc ? g_fwl : g_w1l;

    float acc[4][8][4];
    #pragma unroll
    for (int mi = 0; mi < 4; mi++)
        #pragma unroll
        for (int ni = 0; ni < 8; ni++)
            #pragma unroll
            for (int q = 0; q < 4; q++) acc[mi][ni][q] = 0.f;

    // --- cp.async slots ---
    const int arow_ld = tid >> 1;
    const int ac0     = (tid & 1) * 2;
    uint32_t dstA[2], dstB[4];
    size_t srcA[2], srcB[4];
    #pragma unroll
    for (int q = 0; q < 2; q++) {
        const int c = ac0 + q;
        const int cs = c ^ ((arow_ld >> 1) & 3);
        dstA[q] = (uint32_t)(arow_ld * 64 + cs * 16);
        srcA[q] = (size_t)(m0 + arow_ld) * INK + c * 8;
    }
    #pragma unroll
    for (int q = 0; q < 4; q++) {
        const int cs = q ^ ((tid >> 1) & 3);
        dstB[q] = (uint32_t)(16384 + tid * 64 + cs * 16);
        srcB[q] = (size_t)(n0 + tid) * INK + q * 8;
    }

    auto do_load = [&](int stage, int kt) {
        const uint32_t base = sm_u + stage * STAGE_BYTES;
        const size_t koff = (size_t)kt * BK;
        #pragma unroll
        for (int q = 0; q < 2; q++) {
            cpasync16(base + dstA[q],        g_xh + srcA[q] + koff);
            cpasync16(base + 8192 + dstA[q], g_xl + srcA[q] + koff);
        }
        #pragma unroll
        for (int q = 0; q < 4; q++) {
            cpasync16(base + dstB[q],         Bh + srcB[q] + koff);
            cpasync16(base + 16384 + dstB[q], Bl + srcB[q] + koff);
        }
    };

    // --- ldmatrix lane addressing ---
    const int a_r  = (lane & 7) + ((lane >> 3) & 1) * 8;
    const int a_kh = (lane >> 4) & 1;
    uint32_t aRowOff[4]; int aXor[4];
    #pragma unroll
    for (int mi = 0; mi < 4; mi++) {
        const int m_r = warpm * 64 + mi * 16 + a_r;
        aRowOff[mi] = (uint32_t)(m_r * 64);
        aXor[mi] = (m_r >> 1) & 3;
    }
    const int b_r  = (lane & 7) + ((lane >> 4) & 1) * 8;
    const int b_kh = (lane >> 3) & 1;
    uint32_t bRowOff[4]; int bXor[4];
    #pragma unroll
    for (int bq = 0; bq < 4; bq++) {
        const int n_r = warpn * 64 + bq * 16 + b_r;
        bRowOff[bq] = (uint32_t)(16384 + n_r * 64);
        bXor[bq] = (n_r >> 1) & 3;
    }

    auto compute = [&](int stage) {
        const uint32_t base = sm_u + stage * STAGE_BYTES;
        #pragma unroll
        for (int ks = 0; ks < 2; ks++) {
            uint32_t ah[4][4], al[4][4], bb[4][4];
            #pragma unroll
            for (int mi = 0; mi < 4; mi++) {
                const uint32_t ch = (uint32_t)(((ks * 2 + a_kh) ^ aXor[mi]) << 4);
                ldsm4(ah[mi][0], ah[mi][1], ah[mi][2], ah[mi][3],
                      base + aRowOff[mi] + ch);
            }
            #pragma unroll
            for (int mi = 0; mi < 4; mi++) {
                const uint32_t ch = (uint32_t)(((ks * 2 + a_kh) ^ aXor[mi]) << 4);
                ldsm4(al[mi][0], al[mi][1], al[mi][2], al[mi][3],
                      base + 8192 + aRowOff[mi] + ch);
            }
            // Bh
            #pragma unroll
            for (int bq = 0; bq < 4; bq++) {
                const uint32_t ch = (uint32_t)(((ks * 2 + b_kh) ^ bXor[bq]) << 4);
                ldsm4(bb[bq][0], bb[bq][1], bb[bq][2], bb[bq][3],
                      base + bRowOff[bq] + ch);
            }
            #pragma unroll
            for (int mi = 0; mi < 4; mi++)
                #pragma unroll
                for (int ni = 0; ni < 8; ni++)
                    mma16816(acc[mi][ni], ah[mi], &bb[ni >> 1][(ni & 1) * 2]);
            #pragma unroll
            for (int mi = 0; mi < 4; mi++)
                #pragma unroll
                for (int ni = 0; ni < 8; ni++)
                    mma16816(acc[mi][ni], al[mi], &bb[ni >> 1][(ni & 1) * 2]);
            // Bl (reuse bb registers)
            #pragma unroll
            for (int bq = 0; bq < 4; bq++) {
                const uint32_t ch = (uint32_t)(((ks * 2 + b_kh) ^ bXor[bq]) << 4);
                ldsm4(bb[bq][0], bb[bq][1], bb[bq][2], bb[bq][3],
                      base + 16384 + bRowOff[bq] + ch);
            }
            #pragma unroll
            for (int mi = 0; mi < 4; mi++)
                #pragma unroll
                for (int ni = 0; ni < 8; ni++)
                    mma16816(acc[mi][ni], ah[mi], &bb[ni >> 1][(ni & 1) * 2]);
        }
    };

    // --- pipeline: 2 ahead, 3 stages ---
    do_load(0, 0); cpcommit();
    do_load(1, 1); cpcommit();

    for (int it = 0; it < NIT; it++) {
        asm volatile("cp.async.wait_group 1;" ::: "memory");
        __syncthreads();
        compute(it % NSTG);
        if (it + 2 < NIT) do_load((it + 2) % NSTG, it + 2);
        cpcommit();
    }

    // --- epilogue ---
    const int gid = lane >> 2;
    const int tq  = lane & 3;

    if (!is_fc) {
        #pragma unroll
        for (int ni = 0; ni < 8; ni++) {
            const int nb = n0 + warpn * 64 + ni * 8 + tq * 2;
            const float b1v0 = __ldg(&b1[nb]),     w2v0 = __ldg(&W2[nb]);
            const float b1v1 = __ldg(&b1[nb + 1]), w2v1 = __ldg(&W2[nb + 1]);
            const int dec = nb >> 2;
            const float b2v = __ldg(&b2[dec]);
            #pragma unroll
            for (int mi = 0; mi < 4; mi++) {
                #pragma unroll
                for (int h2 = 0; h2 < 2; h2++) {
                    const int gm = m0 + warpm * 64 + mi * 16 + gid + h2 * 8;
                    float v0 = acc[mi][ni][h2 * 2 + 0] + b1v0;
                    float v1 = acc[mi][ni][h2 * 2 + 1] + b1v1;
                    v0 = v0 >= 0.f ? v0 : NEG_SLOPE * v0;
                    v1 = v1 >= 0.f ? v1 : NEG_SLOPE * v1;
                    float p = v0 * w2v0 + v1 * w2v1;
                    p += __shfl_xor_sync(0xffffffffu, p, 1);
                    if ((lane & 1) == 0)
                        out2[(size_t)gm * ODEC + dec] = p + b2v;
                }
            }
        }
    } else {
        #pragma unroll
        for (int ni = 0; ni < 8; ni++) {
            const int nb = n0 + warpn * 64 + ni * 8 + tq * 2;
            float fb0 = 0.f, fb1 = 0.f;
            if (nb < NCF)     fb0 = __ldg(&fcb[nb]);
            if (nb + 1 < NCF) fb1 = __ldg(&fcb[nb + 1]);
            #pragma unroll
            for (int mi = 0; mi < 4; mi++) {
                #pragma unroll
                for (int h2 = 0; h2 < 2; h2++) {
                    const int gm = m0 + warpm * 64 + mi * 16 + gid + h2 * 8;
                    if (nb < NCF)
                        out1[(size_t)gm * NCF + nb]     = acc[mi][ni][h2 * 2 + 0] + fb0;
                    if (nb + 1 < NCF)
                        out1[(size_t)gm * NCF + nb + 1] = acc[mi][ni][h2 * 2 + 1] + fb1;
                }
            }
        }
    }
}

// ---------------------------------------------------------------------------
extern "C" void kernel_launch(void* const* d_in, const int* in_sizes, int n_in,
                              void* d_out, int out_size)
{
    const float* x   = (const float*)d_in[0];
    const float* fcW = (const float*)d_in[1];
    const float* fcb = (const float*)d_in[2];
    const float* W1  = (const float*)d_in[3];
    const float* b1  = (const float*)d_in[4];
    const float* W2  = (const float*)d_in[5];
    const float* b2  = (const float*)d_in[6];

    float* out1 = (float*)d_out;              // x1 [256,1000]
    float* out2 = out1 + BSZ * NCF;           // x2 [256,4096]

    cudaFuncSetAttribute(mma_all, cudaFuncAttributeMaxDynamicSharedMemorySize, SMEM_DYN);

    conv_all<<<5632, 256>>>(x, W1, fcW);
    mma_all<<<dim3(68, 2), 256, SMEM_DYN>>>(b1, W2, b2, fcb, out1, out2);
}

// round 14
// speedup vs baseline: 2.4523x; 1.2001x over previous
#include <cuda_runtime.h>
#include <cuda_bf16.h>
#include <cstdint>
#include <cstddef>

typedef unsigned long long ull;

#define BSZ   256
#define INK   2048
#define NCF   1000
#define NCP   1024
#define ODEC  4096
#define NDEC  16384
#define NEG_SLOPE 0.1f

#define BK    32
#define NIT   (INK / BK)       // 64 iterations, all 3 products per ktile
#define STAGE_BYTES 49152      // Ah 8K @0, Al 8K @8192, Bh 16K @16384, Bl 16K @32768
#define NSTG  3
#define SMEM_DYN (NSTG * STAGE_BYTES)
#define NTHR  512

// bf16 hi/lo scratch
__device__ __nv_bfloat16 g_xh[BSZ * INK];
__device__ __nv_bfloat16 g_xl[BSZ * INK];
__device__ __nv_bfloat16 g_w1h[(size_t)NDEC * INK];
__device__ __nv_bfloat16 g_w1l[(size_t)NDEC * INK];
__device__ __nv_bfloat16 g_fwh[(size_t)NCP * INK];
__device__ __nv_bfloat16 g_fwl[(size_t)NCP * INK];

// ---------------------------------------------------------------------------
__device__ __forceinline__ uint32_t smem_u32(const void* p) {
    return (uint32_t)__cvta_generic_to_shared(p);
}
__device__ __forceinline__ void cpasync16(uint32_t dst, const void* src) {
    asm volatile("cp.async.cg.shared.global [%0], [%1], 16;" :: "r"(dst), "l"(src));
}
__device__ __forceinline__ void cpcommit() {
    asm volatile("cp.async.commit_group;");
}
__device__ __forceinline__ void ldsm4(uint32_t& r0, uint32_t& r1, uint32_t& r2,
                                      uint32_t& r3, uint32_t addr) {
    asm volatile("ldmatrix.sync.aligned.m8n8.x4.shared.b16 {%0,%1,%2,%3}, [%4];"
                 : "=r"(r0), "=r"(r1), "=r"(r2), "=r"(r3) : "r"(addr));
}
__device__ __forceinline__ void mma16816(float* d, const uint32_t* a, const uint32_t* b) {
    asm volatile(
        "mma.sync.aligned.m16n8k16.row.col.f32.bf16.bf16.f32 "
        "{%0,%1,%2,%3}, {%4,%5,%6,%7}, {%8,%9}, {%0,%1,%2,%3};"
        : "+f"(d[0]), "+f"(d[1]), "+f"(d[2]), "+f"(d[3])
        : "r"(a[0]), "r"(a[1]), "r"(a[2]), "r"(a[3]), "r"(b[0]), "r"(b[1]));
}

__device__ __forceinline__ ull pk4(__nv_bfloat16 a, __nv_bfloat16 b,
                                   __nv_bfloat16 c, __nv_bfloat16 d) {
    return (ull)__bfloat16_as_ushort(a)
         | ((ull)__bfloat16_as_ushort(b) << 16)
         | ((ull)__bfloat16_as_ushort(c) << 32)
         | ((ull)__bfloat16_as_ushort(d) << 48);
}
__device__ __forceinline__ uint32_t pk2(__nv_bfloat16 a, __nv_bfloat16 b) {
    return (uint32_t)__bfloat16_as_ushort(a)
         | ((uint32_t)__bfloat16_as_ushort(b) << 16);
}
__device__ __forceinline__ void split1(float v, __nv_bfloat16& h, __nv_bfloat16& l) {
    h = __float2bfloat16_rn(v);
    l = __float2bfloat16_rn(v - __bfloat162float(h));
}

// ---------------------------------------------------------------------------
// Merged conversion kernel (unchanged — near BW-bound)
// ---------------------------------------------------------------------------
__global__ __launch_bounds__(256)
void conv_all(const float* __restrict__ x, const float* __restrict__ W1,
              const float* __restrict__ fcW)
{
    __shared__ uint32_t sh_hi[4][1024];
    __shared__ uint32_t sh_lo[4][1024];

    const int bx = blockIdx.x;
    const int t = threadIdx.x;

    if (bx < 4096) {
        const int o = bx;
        const float4* src = (const float4*)(W1 + (size_t)o * 8192);
        #pragma unroll
        for (int q = 0; q < 4; q++) {
            const int j = t + q * 256;
            float4 v0 = src[2 * j];
            float4 v1 = src[2 * j + 1];
            float a0[4] = {v0.x, v0.y, v0.z, v0.w};
            float a1[4] = {v1.x, v1.y, v1.z, v1.w};
            #pragma unroll
            for (int h = 0; h < 4; h++) {
                __nv_bfloat16 h0, l0, h1, l1;
                split1(a0[h], h0, l0);
                split1(a1[h], h1, l1);
                sh_hi[h][j] = pk2(h0, h1);
                sh_lo[h][j] = pk2(l0, l1);
            }
        }
        __syncthreads();
        #pragma unroll
        for (int h = 0; h < 4; h++) {
            const size_t row = (size_t)(o * 4 + h) * INK;
            ((uint4*)(g_w1h + row))[t] = ((const uint4*)sh_hi[h])[t];
            ((uint4*)(g_w1l + row))[t] = ((const uint4*)sh_lo[h])[t];
        }
    } else if (bx < 4608) {
        const int g = (bx - 4096) * 256 + t;
        float4 v = ((const float4*)x)[g];
        __nv_bfloat16 h0,h1,h2,h3,l0,l1,l2,l3;
        split1(v.x,h0,l0); split1(v.y,h1,l1); split1(v.z,h2,l2); split1(v.w,h3,l3);
        ((ull*)g_xh)[g] = pk4(h0,h1,h2,h3);
        ((ull*)g_xl)[g] = pk4(l0,l1,l2,l3);
    } else {
        const int n = bx - 4608;
        const int base = t * 8;
        __nv_bfloat16 hb[8], lb[8];
        if (n < NCF) {
            const float4* src = (const float4*)(fcW + (size_t)n * INK + base);
            float4 a = src[0], b = src[1];
            float vv[8] = {a.x,a.y,a.z,a.w,b.x,b.y,b.z,b.w};
            #pragma unroll
            for (int j = 0; j < 8; j++) split1(vv[j], hb[j], lb[j]);
        } else {
            #pragma unroll
            for (int j = 0; j < 8; j++) { hb[j] = __float2bfloat16(0.f); lb[j] = __float2bfloat16(0.f); }
        }
        ull* dh = (ull*)(g_fwh + (size_t)n * INK + base);
        ull* dl = (ull*)(g_fwl + (size_t)n * INK + base);
        dh[0] = pk4(hb[0],hb[1],hb[2],hb[3]); dh[1] = pk4(hb[4],hb[5],hb[6],hb[7]);
        dl[0] = pk4(lb[0],lb[1],lb[2],lb[3]); dl[1] = pk4(lb[4],lb[5],lb[6],lb[7]);
    }
}

// ---------------------------------------------------------------------------
// Fused mma kernel: CTA 128m x 256n, 16 warps of 32m x 64n (512 threads).
// All 3 products per ktile: (ah*bh) + (al*bh) with bh live, then (ah*bl).
// ---------------------------------------------------------------------------
__global__ __launch_bounds__(NTHR, 1)
void mma_all(const float* __restrict__ b1, const float* __restrict__ W2,
             const float* __restrict__ b2, const float* __restrict__ fcb,
             float* __restrict__ out1, float* __restrict__ out2)
{
    extern __shared__ __align__(1024) char smbuf[];

    const int tid = threadIdx.x;
    const int lane = tid & 31;
    const int w = tid >> 5;
    const int warpm = w >> 2;       // 0..3  (32 m each)
    const int warpn = w & 3;        // 0..3  (64 n each)
    const bool is_fc = blockIdx.x >= 64;
    const int m0 = blockIdx.y * 128;
    const int n0 = (is_fc ? (blockIdx.x - 64) : blockIdx.x) * 256;
    const uint32_t sm_u = smem_u32(smbuf);

    const __nv_bfloat16* Bh = is_fc ? g_fwh : g_w1h;
    const __nv_bfloat16* Bl = is_fc ? g_fwl : g_w1l;

    float acc[2][8][4];
    #pragma unroll
    for (int mi = 0; mi < 2; mi++)
        #pragma unroll
        for (int ni = 0; ni < 8; ni++)
            #pragma unroll
            for (int q = 0; q < 4; q++) acc[mi][ni][q] = 0.f;

    // --- cp.async slots: A 1 chunk/thread per half, B 2 chunks/thread per half ---
    const int arow_ld = tid >> 2;               // 0..127
    const int ac      = tid & 3;
    const int acs     = ac ^ ((arow_ld >> 1) & 3);
    const uint32_t dstA = (uint32_t)(arow_ld * 64 + acs * 16);
    const size_t   srcA = (size_t)(m0 + arow_ld) * INK + ac * 8;

    const int brow_ld = tid >> 1;               // 0..255
    uint32_t dstB[2];
    size_t srcB[2];
    #pragma unroll
    for (int q = 0; q < 2; q++) {
        const int c = (tid & 1) * 2 + q;
        const int cs = c ^ ((brow_ld >> 1) & 3);
        dstB[q] = (uint32_t)(16384 + brow_ld * 64 + cs * 16);
        srcB[q] = (size_t)(n0 + brow_ld) * INK + c * 8;
    }

    auto do_load = [&](int stage, int kt) {
        const uint32_t base = sm_u + stage * STAGE_BYTES;
        const size_t koff = (size_t)kt * BK;
        cpasync16(base + dstA,        g_xh + srcA + koff);
        cpasync16(base + 8192 + dstA, g_xl + srcA + koff);
        #pragma unroll
        for (int q = 0; q < 2; q++) {
            cpasync16(base + dstB[q],         Bh + srcB[q] + koff);
            cpasync16(base + 16384 + dstB[q], Bl + srcB[q] + koff);
        }
    };

    // --- ldmatrix lane addressing ---
    const int a_r  = (lane & 7) + ((lane >> 3) & 1) * 8;
    const int a_kh = (lane >> 4) & 1;
    uint32_t aRowOff[2]; int aXor[2];
    #pragma unroll
    for (int mi = 0; mi < 2; mi++) {
        const int m_r = warpm * 32 + mi * 16 + a_r;
        aRowOff[mi] = (uint32_t)(m_r * 64);
        aXor[mi] = (m_r >> 1) & 3;
    }
    const int b_r  = (lane & 7) + ((lane >> 4) & 1) * 8;
    const int b_kh = (lane >> 3) & 1;
    uint32_t bRowOff[4]; int bXor[4];
    #pragma unroll
    for (int bq = 0; bq < 4; bq++) {
        const int n_r = warpn * 64 + bq * 16 + b_r;
        bRowOff[bq] = (uint32_t)(16384 + n_r * 64);
        bXor[bq] = (n_r >> 1) & 3;
    }

    auto compute = [&](int stage) {
        const uint32_t base = sm_u + stage * STAGE_BYTES;
        #pragma unroll
        for (int ks = 0; ks < 2; ks++) {
            uint32_t ah[2][4], al[2][4], bb[4][4];
            #pragma unroll
            for (int mi = 0; mi < 2; mi++) {
                const uint32_t ch = (uint32_t)(((ks * 2 + a_kh) ^ aXor[mi]) << 4);
                ldsm4(ah[mi][0], ah[mi][1], ah[mi][2], ah[mi][3],
                      base + aRowOff[mi] + ch);
                ldsm4(al[mi][0], al[mi][1], al[mi][2], al[mi][3],
                      base + 8192 + aRowOff[mi] + ch);
            }
            #pragma unroll
            for (int bq = 0; bq < 4; bq++) {
                const uint32_t ch = (uint32_t)(((ks * 2 + b_kh) ^ bXor[bq]) << 4);
                ldsm4(bb[bq][0], bb[bq][1], bb[bq][2], bb[bq][3],
                      base + bRowOff[bq] + ch);
            }
            #pragma unroll
            for (int mi = 0; mi < 2; mi++)
                #pragma unroll
                for (int ni = 0; ni < 8; ni++)
                    mma16816(acc[mi][ni], ah[mi], &bb[ni >> 1][(ni & 1) * 2]);
            #pragma unroll
            for (int mi = 0; mi < 2; mi++)
                #pragma unroll
                for (int ni = 0; ni < 8; ni++)
                    mma16816(acc[mi][ni], al[mi], &bb[ni >> 1][(ni & 1) * 2]);
            // Bl (reuse bb registers)
            #pragma unroll
            for (int bq = 0; bq < 4; bq++) {
                const uint32_t ch = (uint32_t)(((ks * 2 + b_kh) ^ bXor[bq]) << 4);
                ldsm4(bb[bq][0], bb[bq][1], bb[bq][2], bb[bq][3],
                      base + 16384 + bRowOff[bq] + ch);
            }
            #pragma unroll
            for (int mi = 0; mi < 2; mi++)
                #pragma unroll
                for (int ni = 0; ni < 8; ni++)
                    mma16816(acc[mi][ni], ah[mi], &bb[ni >> 1][(ni & 1) * 2]);
        }
    };

    // --- pipeline: 2 ahead, 3 stages ---
    do_load(0, 0); cpcommit();
    do_load(1, 1); cpcommit();

    for (int it = 0; it < NIT; it++) {
        asm volatile("cp.async.wait_group 1;" ::: "memory");
        __syncthreads();
        compute(it % NSTG);
        if (it + 2 < NIT) do_load((it + 2) % NSTG, it + 2);
        cpcommit();
    }

    // --- epilogue ---
    const int gid = lane >> 2;
    const int tq  = lane & 3;

    if (!is_fc) {
        #pragma unroll
        for (int ni = 0; ni < 8; ni++) {
            const int nb = n0 + warpn * 64 + ni * 8 + tq * 2;
            const float b1v0 = __ldg(&b1[nb]),     w2v0 = __ldg(&W2[nb]);
            const float b1v1 = __ldg(&b1[nb + 1]), w2v1 = __ldg(&W2[nb + 1]);
            const int dec = nb >> 2;
            const float b2v = __ldg(&b2[dec]);
            #pragma unroll
            for (int mi = 0; mi < 2; mi++) {
                #pragma unroll
                for (int h2 = 0; h2 < 2; h2++) {
                    const int gm = m0 + warpm * 32 + mi * 16 + gid + h2 * 8;
                    float v0 = acc[mi][ni][h2 * 2 + 0] + b1v0;
                    float v1 = acc[mi][ni][h2 * 2 + 1] + b1v1;
                    v0 = v0 >= 0.f ? v0 : NEG_SLOPE * v0;
                    v1 = v1 >= 0.f ? v1 : NEG_SLOPE * v1;
                    float p = v0 * w2v0 + v1 * w2v1;
                    p += __shfl_xor_sync(0xffffffffu, p, 1);
                    if ((lane & 1) == 0)
                        out2[(size_t)gm * ODEC + dec] = p + b2v;
                }
            }
        }
    } else {
        #pragma unroll
        for (int ni = 0; ni < 8; ni++) {
            const int nb = n0 + warpn * 64 + ni * 8 + tq * 2;
            float fb0 = 0.f, fb1 = 0.f;
            if (nb < NCF)     fb0 = __ldg(&fcb[nb]);
            if (nb + 1 < NCF) fb1 = __ldg(&fcb[nb + 1]);
            #pragma unroll
            for (int mi = 0; mi < 2; mi++) {
                #pragma unroll
                for (int h2 = 0; h2 < 2; h2++) {
                    const int gm = m0 + warpm * 32 + mi * 16 + gid + h2 * 8;
                    if (nb < NCF)
                        out1[(size_t)gm * NCF + nb]     = acc[mi][ni][h2 * 2 + 0] + fb0;
                    if (nb + 1 < NCF)
                        out1[(size_t)gm * NCF + nb + 1] = acc[mi][ni][h2 * 2 + 1] + fb1;
                }
            }
        }
    }
}

// ---------------------------------------------------------------------------
extern "C" void kernel_launch(void* const* d_in, const int* in_sizes, int n_in,
                              void* d_out, int out_size)
{
    const float* x   = (const float*)d_in[0];
    const float* fcW = (const float*)d_in[1];
    const float* fcb = (const float*)d_in[2];
    const float* W1  = (const float*)d_in[3];
    const float* b1  = (const float*)d_in[4];
    const float* W2  = (const float*)d_in[5];
    const float* b2  = (const float*)d_in[6];

    float* out1 = (float*)d_out;              // x1 [256,1000]
    float* out2 = out1 + BSZ * NCF;           // x2 [256,4096]

    cudaFuncSetAttribute(mma_all, cudaFuncAttributeMaxDynamicSharedMemorySize, SMEM_DYN);

    conv_all<<<5632, 256>>>(x, W1, fcW);
    mma_all<<<dim3(68, 2), NTHR, SMEM_DYN>>>(b1, W2, b2, fcb, out1, out2);
}

// round 15
// speedup vs baseline: 2.5882x; 1.0554x over previous
#include <cuda_runtime.h>
#include <cuda_bf16.h>
#include <cstdint>
#include <cstddef>

typedef unsigned long long ull;

#define BSZ   256
#define INK   2048
#define NCF   1000
#define NCP   1024
#define ODEC  4096
#define NDEC  16384
#define NEG_SLOPE 0.1f

#define BK    64
#define NIT   (INK / BK)       // 32 iterations, all 3 products per ktile
#define STAGE_BYTES 98304      // Ah 16K @0, Al 16K @16384, Bh 32K @32768, Bl 32K @65536
#define NSTG  2
#define SMEM_DYN (NSTG * STAGE_BYTES)
#define NTHR  512

// bf16 hi/lo scratch
__device__ __nv_bfloat16 g_xh[BSZ * INK];
__device__ __nv_bfloat16 g_xl[BSZ * INK];
__device__ __nv_bfloat16 g_w1h[(size_t)NDEC * INK];
__device__ __nv_bfloat16 g_w1l[(size_t)NDEC * INK];
__device__ __nv_bfloat16 g_fwh[(size_t)NCP * INK];
__device__ __nv_bfloat16 g_fwl[(size_t)NCP * INK];

// ---------------------------------------------------------------------------
__device__ __forceinline__ uint32_t smem_u32(const void* p) {
    return (uint32_t)__cvta_generic_to_shared(p);
}
__device__ __forceinline__ void cpasync16(uint32_t dst, const void* src) {
    asm volatile("cp.async.cg.shared.global [%0], [%1], 16;" :: "r"(dst), "l"(src));
}
__device__ __forceinline__ void cpcommit() {
    asm volatile("cp.async.commit_group;");
}
__device__ __forceinline__ void ldsm4(uint32_t& r0, uint32_t& r1, uint32_t& r2,
                                      uint32_t& r3, uint32_t addr) {
    asm volatile("ldmatrix.sync.aligned.m8n8.x4.shared.b16 {%0,%1,%2,%3}, [%4];"
                 : "=r"(r0), "=r"(r1), "=r"(r2), "=r"(r3) : "r"(addr));
}
__device__ __forceinline__ void mma16816(float* d, const uint32_t* a, const uint32_t* b) {
    asm volatile(
        "mma.sync.aligned.m16n8k16.row.col.f32.bf16.bf16.f32 "
        "{%0,%1,%2,%3}, {%4,%5,%6,%7}, {%8,%9}, {%0,%1,%2,%3};"
        : "+f"(d[0]), "+f"(d[1]), "+f"(d[2]), "+f"(d[3])
        : "r"(a[0]), "r"(a[1]), "r"(a[2]), "r"(a[3]), "r"(b[0]), "r"(b[1]));
}

__device__ __forceinline__ ull pk4(__nv_bfloat16 a, __nv_bfloat16 b,
                                   __nv_bfloat16 c, __nv_bfloat16 d) {
    return (ull)__bfloat16_as_ushort(a)
         | ((ull)__bfloat16_as_ushort(b) << 16)
         | ((ull)__bfloat16_as_ushort(c) << 32)
         | ((ull)__bfloat16_as_ushort(d) << 48);
}
__device__ __forceinline__ uint32_t pk2(__nv_bfloat16 a, __nv_bfloat16 b) {
    return (uint32_t)__bfloat16_as_ushort(a)
         | ((uint32_t)__bfloat16_as_ushort(b) << 16);
}
__device__ __forceinline__ void split1(float v, __nv_bfloat16& h, __nv_bfloat16& l) {
    h = __float2bfloat16_rn(v);
    l = __float2bfloat16_rn(v - __bfloat162float(h));
}

// ---------------------------------------------------------------------------
// Merged conversion kernel (unchanged — near BW-bound)
// ---------------------------------------------------------------------------
__global__ __launch_bounds__(256)
void conv_all(const float* __restrict__ x, const float* __restrict__ W1,
              const float* __restrict__ fcW)
{
    __shared__ uint32_t sh_hi[4][1024];
    __shared__ uint32_t sh_lo[4][1024];

    const int bx = blockIdx.x;
    const int t = threadIdx.x;

    if (bx < 4096) {
        const int o = bx;
        const float4* src = (const float4*)(W1 + (size_t)o * 8192);
        #pragma unroll
        for (int q = 0; q < 4; q++) {
            const int j = t + q * 256;
            float4 v0 = src[2 * j];
            float4 v1 = src[2 * j + 1];
            float a0[4] = {v0.x, v0.y, v0.z, v0.w};
            float a1[4] = {v1.x, v1.y, v1.z, v1.w};
            #pragma unroll
            for (int h = 0; h < 4; h++) {
                __nv_bfloat16 h0, l0, h1, l1;
                split1(a0[h], h0, l0);
                split1(a1[h], h1, l1);
                sh_hi[h][j] = pk2(h0, h1);
                sh_lo[h][j] = pk2(l0, l1);
            }
        }
        __syncthreads();
        #pragma unroll
        for (int h = 0; h < 4; h++) {
            const size_t row = (size_t)(o * 4 + h) * INK;
            ((uint4*)(g_w1h + row))[t] = ((const uint4*)sh_hi[h])[t];
            ((uint4*)(g_w1l + row))[t] = ((const uint4*)sh_lo[h])[t];
        }
    } else if (bx < 4608) {
        const int g = (bx - 4096) * 256 + t;
        float4 v = ((const float4*)x)[g];
        __nv_bfloat16 h0,h1,h2,h3,l0,l1,l2,l3;
        split1(v.x,h0,l0); split1(v.y,h1,l1); split1(v.z,h2,l2); split1(v.w,h3,l3);
        ((ull*)g_xh)[g] = pk4(h0,h1,h2,h3);
        ((ull*)g_xl)[g] = pk4(l0,l1,l2,l3);
    } else {
        const int n = bx - 4608;
        const int base = t * 8;
        __nv_bfloat16 hb[8], lb[8];
        if (n < NCF) {
            const float4* src = (const float4*)(fcW + (size_t)n * INK + base);
            float4 a = src[0], b = src[1];
            float vv[8] = {a.x,a.y,a.z,a.w,b.x,b.y,b.z,b.w};
            #pragma unroll
            for (int j = 0; j < 8; j++) split1(vv[j], hb[j], lb[j]);
        } else {
            #pragma unroll
            for (int j = 0; j < 8; j++) { hb[j] = __float2bfloat16(0.f); lb[j] = __float2bfloat16(0.f); }
        }
        ull* dh = (ull*)(g_fwh + (size_t)n * INK + base);
        ull* dl = (ull*)(g_fwl + (size_t)n * INK + base);
        dh[0] = pk4(hb[0],hb[1],hb[2],hb[3]); dh[1] = pk4(hb[4],hb[5],hb[6],hb[7]);
        dl[0] = pk4(lb[0],lb[1],lb[2],lb[3]); dl[1] = pk4(lb[4],lb[5],lb[6],lb[7]);
    }
}

// ---------------------------------------------------------------------------
// Fused mma kernel: CTA 128m x 256n, 16 warps of 32m x 64n (512 threads).
// BK=64, 2-stage double buffer, 32 iterations.
// All 3 products per ktile: (ah*bh) + (al*bh) with bh live, then (ah*bl).
// smem rows are 128B (8 x 16B chunks); swizzle: chunk ^= (row & 7).
// ---------------------------------------------------------------------------
__global__ __launch_bounds__(NTHR, 1)
void mma_all(const float* __restrict__ b1, const float* __restrict__ W2,
             const float* __restrict__ b2, const float* __restrict__ fcb,
             float* __restrict__ out1, float* __restrict__ out2)
{
    extern __shared__ __align__(1024) char smbuf[];

    const int tid = threadIdx.x;
    const int lane = tid & 31;
    const int w = tid >> 5;
    const int warpm = w >> 2;       // 0..3  (32 m each)
    const int warpn = w & 3;        // 0..3  (64 n each)
    const bool is_fc = blockIdx.x >= 64;
    const int m0 = blockIdx.y * 128;
    const int n0 = (is_fc ? (blockIdx.x - 64) : blockIdx.x) * 256;
    const uint32_t sm_u = smem_u32(smbuf);

    const __nv_bfloat16* Bh = is_fc ? g_fwh : g_w1h;
    const __nv_bfloat16* Bl = is_fc ? g_fwl : g_w1l;

    float acc[2][8][4];
    #pragma unroll
    for (int mi = 0; mi < 2; mi++)
        #pragma unroll
        for (int ni = 0; ni < 8; ni++)
            #pragma unroll
            for (int q = 0; q < 4; q++) acc[mi][ni][q] = 0.f;

    // --- cp.async slots ---
    // A: 128 rows x 8 chunks = 1024 -> 2/thread (per Ah/Al buffer)
    uint32_t dstA[2]; size_t srcA[2];
    #pragma unroll
    for (int q = 0; q < 2; q++) {
        const int g = tid + q * NTHR;
        const int r = g >> 3, c = g & 7;
        dstA[q] = (uint32_t)(r * 128 + (c ^ (r & 7)) * 16);
        srcA[q] = (size_t)(m0 + r) * INK + c * 8;
    }
    // B: 256 rows x 8 chunks = 2048 -> 4/thread (per Bh/Bl buffer)
    uint32_t dstB[4]; size_t srcB[4];
    #pragma unroll
    for (int q = 0; q < 4; q++) {
        const int g = tid + q * NTHR;
        const int r = g >> 3, c = g & 7;
        dstB[q] = (uint32_t)(32768 + r * 128 + (c ^ (r & 7)) * 16);
        srcB[q] = (size_t)(n0 + r) * INK + c * 8;
    }

    auto do_load = [&](int stage, int kt) {
        const uint32_t base = sm_u + stage * STAGE_BYTES;
        const size_t koff = (size_t)kt * BK;
        #pragma unroll
        for (int q = 0; q < 2; q++) {
            cpasync16(base + dstA[q],         g_xh + srcA[q] + koff);
            cpasync16(base + 16384 + dstA[q], g_xl + srcA[q] + koff);
        }
        #pragma unroll
        for (int q = 0; q < 4; q++) {
            cpasync16(base + dstB[q],         Bh + srcB[q] + koff);
            cpasync16(base + 32768 + dstB[q], Bl + srcB[q] + koff);
        }
    };

    // --- ldmatrix lane addressing ---
    const int a_r  = (lane & 7) + ((lane >> 3) & 1) * 8;
    const int a_kh = (lane >> 4) & 1;
    const int axr  = lane & 7;                 // row&7 for swizzle (mi-invariant)
    uint32_t aRowOff[2];
    #pragma unroll
    for (int mi = 0; mi < 2; mi++)
        aRowOff[mi] = (uint32_t)((warpm * 32 + mi * 16 + a_r) * 128);

    const int b_r  = (lane & 7) + ((lane >> 4) & 1) * 8;
    const int b_kh = (lane >> 3) & 1;
    const int bxr  = lane & 7;
    uint32_t bRowOff[4];
    #pragma unroll
    for (int bq = 0; bq < 4; bq++)
        bRowOff[bq] = (uint32_t)(32768 + (warpn * 64 + bq * 16 + b_r) * 128);

    auto compute = [&](int stage) {
        const uint32_t base = sm_u + stage * STAGE_BYTES;
        #pragma unroll
        for (int ks = 0; ks < 4; ks++) {
            uint32_t ah[2][4], al[2][4], bb[4][4];
            const uint32_t chA = (uint32_t)(((ks * 2 + a_kh) ^ axr) << 4);
            const uint32_t chB = (uint32_t)(((ks * 2 + b_kh) ^ bxr) << 4);
            #pragma unroll
            for (int mi = 0; mi < 2; mi++) {
                ldsm4(ah[mi][0], ah[mi][1], ah[mi][2], ah[mi][3],
                      base + aRowOff[mi] + chA);
                ldsm4(al[mi][0], al[mi][1], al[mi][2], al[mi][3],
                      base + 16384 + aRowOff[mi] + chA);
            }
            #pragma unroll
            for (int bq = 0; bq < 4; bq++)
                ldsm4(bb[bq][0], bb[bq][1], bb[bq][2], bb[bq][3],
                      base + bRowOff[bq] + chB);
            #pragma unroll
            for (int mi = 0; mi < 2; mi++)
                #pragma unroll
                for (int ni = 0; ni < 8; ni++)
                    mma16816(acc[mi][ni], ah[mi], &bb[ni >> 1][(ni & 1) * 2]);
            #pragma unroll
            for (int mi = 0; mi < 2; mi++)
                #pragma unroll
                for (int ni = 0; ni < 8; ni++)
                    mma16816(acc[mi][ni], al[mi], &bb[ni >> 1][(ni & 1) * 2]);
            // Bl (reuse bb registers)
            #pragma unroll
            for (int bq = 0; bq < 4; bq++)
                ldsm4(bb[bq][0], bb[bq][1], bb[bq][2], bb[bq][3],
                      base + 32768 + bRowOff[bq] + chB);
            #pragma unroll
            for (int mi = 0; mi < 2; mi++)
                #pragma unroll
                for (int ni = 0; ni < 8; ni++)
                    mma16816(acc[mi][ni], ah[mi], &bb[ni >> 1][(ni & 1) * 2]);
        }
    };

    // --- 2-stage double buffer: wait -> sync -> issue next -> compute ---
    do_load(0, 0); cpcommit();

    for (int it = 0; it < NIT; it++) {
        asm volatile("cp.async.wait_group 0;" ::: "memory");
        __syncthreads();
        if (it + 1 < NIT) { do_load((it + 1) & 1, it + 1); cpcommit(); }
        compute(it & 1);
    }

    // --- epilogue ---
    const int gid = lane >> 2;
    const int tq  = lane & 3;

    if (!is_fc) {
        #pragma unroll
        for (int ni = 0; ni < 8; ni++) {
            const int nb = n0 + warpn * 64 + ni * 8 + tq * 2;
            const float b1v0 = __ldg(&b1[nb]),     w2v0 = __ldg(&W2[nb]);
            const float b1v1 = __ldg(&b1[nb + 1]), w2v1 = __ldg(&W2[nb + 1]);
            const int dec = nb >> 2;
            const float b2v = __ldg(&b2[dec]);
            #pragma unroll
            for (int mi = 0; mi < 2; mi++) {
                #pragma unroll
                for (int h2 = 0; h2 < 2; h2++) {
                    const int gm = m0 + warpm * 32 + mi * 16 + gid + h2 * 8;
                    float v0 = acc[mi][ni][h2 * 2 + 0] + b1v0;
                    float v1 = acc[mi][ni][h2 * 2 + 1] + b1v1;
                    v0 = v0 >= 0.f ? v0 : NEG_SLOPE * v0;
                    v1 = v1 >= 0.f ? v1 : NEG_SLOPE * v1;
                    float p = v0 * w2v0 + v1 * w2v1;
                    p += __shfl_xor_sync(0xffffffffu, p, 1);
                    if ((lane & 1) == 0)
                        out2[(size_t)gm * ODEC + dec] = p + b2v;
                }
            }
        }
    } else {
        #pragma unroll
        for (int ni = 0; ni < 8; ni++) {
            const int nb = n0 + warpn * 64 + ni * 8 + tq * 2;
            float fb0 = 0.f, fb1 = 0.f;
            if (nb < NCF)     fb0 = __ldg(&fcb[nb]);
            if (nb + 1 < NCF) fb1 = __ldg(&fcb[nb + 1]);
            #pragma unroll
            for (int mi = 0; mi < 2; mi++) {
                #pragma unroll
                for (int h2 = 0; h2 < 2; h2++) {
                    const int gm = m0 + warpm * 32 + mi * 16 + gid + h2 * 8;
                    if (nb < NCF)
                        out1[(size_t)gm * NCF + nb]     = acc[mi][ni][h2 * 2 + 0] + fb0;
                    if (nb + 1 < NCF)
                        out1[(size_t)gm * NCF + nb + 1] = acc[mi][ni][h2 * 2 + 1] + fb1;
                }
            }
        }
    }
}

// ---------------------------------------------------------------------------
extern "C" void kernel_launch(void* const* d_in, const int* in_sizes, int n_in,
                              void* d_out, int out_size)
{
    const float* x   = (const float*)d_in[0];
    const float* fcW = (const float*)d_in[1];
    const float* fcb = (const float*)d_in[2];
    const float* W1  = (const float*)d_in[3];
    const float* b1  = (const float*)d_in[4];
    const float* W2  = (const float*)d_in[5];
    const float* b2  = (const float*)d_in[6];

    float* out1 = (float*)d_out;              // x1 [256,1000]
    float* out2 = out1 + BSZ * NCF;           // x2 [256,4096]

    cudaFuncSetAttribute(mma_all, cudaFuncAttributeMaxDynamicSharedMemorySize, SMEM_DYN);

    conv_all<<<5632, 256>>>(x, W1, fcW);
    mma_all<<<dim3(68, 2), NTHR, SMEM_DYN>>>(b1, W2, b2, fcb, out1, out2);
}